// round 7
// baseline (speedup 1.0000x reference)
#include <cuda_runtime.h>

// ---------------------------------------------------------------------------
// CML2DWithStats, fused temporal-blocking kernel (Round 7).
// Geometry identical to Round 6 (197us): one CTA per (batch*chan, 32-row
// band); 66-logical-row x 264-col double-buffered smem window; shrinking
// cone [s+1, 62-s]; contiguous-quad row ownership with register rolling.
//
// Round-7 change (issue-bound, 59.3%, fma 36%): packed f32x2 arithmetic.
// Outputs pair along x as (g0,g1),(g2,g3). Row window m[0..5] -> 5
// overlapping pairs; 9-tap conv + drive = 10 fma.rn.f32x2 per output-pair
// (was 40 scalar FFMA + 8 misc per row). Stats and logistic map also packed.
// Clamp stays scalar FMNMX on the pair halves.
// ---------------------------------------------------------------------------

typedef unsigned long long u64;

#define SSTR  264
#define LROWS 66
#define NBUF  (LROWS * SSTR)
#define PL    8388608L

// ---- f32x2 helpers --------------------------------------------------------
__device__ __forceinline__ u64 pk2(float lo, float hi) {
    u64 r; asm("mov.b64 %0, {%1, %2};" : "=l"(r) : "f"(lo), "f"(hi)); return r;
}
__device__ __forceinline__ void upk2(u64 v, float& lo, float& hi) {
    asm("mov.b64 {%0, %1}, %2;" : "=f"(lo), "=f"(hi) : "l"(v));
}
__device__ __forceinline__ u64 fma2(u64 a, u64 b, u64 c) {
    u64 d; asm("fma.rn.f32x2 %0, %1, %2, %3;" : "=l"(d) : "l"(a), "l"(b), "l"(c)); return d;
}
__device__ __forceinline__ u64 mul2(u64 a, u64 b) {
    u64 d; asm("mul.rn.f32x2 %0, %1, %2;" : "=l"(d) : "l"(a), "l"(b)); return d;
}
__device__ __forceinline__ u64 add2(u64 a, u64 b) {
    u64 d; asm("add.rn.f32x2 %0, %1, %2;" : "=l"(d) : "l"(a), "l"(b)); return d;
}

// Row window as 5 overlapping pairs P_k = (m_k, m_{k+1}) built from one
// LDS.128 + 2 shuffles (warp-uniform callers only).
__device__ __forceinline__ void load6p(const float* __restrict__ p, int lane, u64 w[5]) {
    float4 v = *reinterpret_cast<const float4*>(p);
    float left  = __shfl_up_sync(0xffffffffu, v.w, 1);
    float right = __shfl_down_sync(0xffffffffu, v.x, 1);
    if (lane == 0)  left  = p[-1];
    if (lane == 31) right = p[4];
    w[0] = pk2(left, v.x); w[1] = pk2(v.x, v.y); w[2] = pk2(v.y, v.z);
    w[3] = pk2(v.z, v.w);  w[4] = pk2(v.w, right);
}

// Packed folded update: g = sum(W .* mapped_nbr) + 0.15*drive, clamped.
// Output-pair j01 uses pairs [0,1,2] of each window; j23 uses [2,3,4].
__device__ __forceinline__ void taps2(
    const u64* __restrict__ Wp,
    const u64 A[5], const u64 B[5], const u64 C[5],
    u64 dd01, u64 dd23, u64 c015, float g[4])
{
    u64 t01 = mul2(Wp[0], A[0]);
    t01 = fma2(Wp[1], A[1], t01);
    t01 = fma2(Wp[2], A[2], t01);
    t01 = fma2(Wp[3], B[0], t01);
    t01 = fma2(Wp[4], B[1], t01);
    t01 = fma2(Wp[5], B[2], t01);
    t01 = fma2(Wp[6], C[0], t01);
    t01 = fma2(Wp[7], C[1], t01);
    t01 = fma2(Wp[8], C[2], t01);
    t01 = fma2(c015, dd01, t01);

    u64 t23 = mul2(Wp[0], A[2]);
    t23 = fma2(Wp[1], A[3], t23);
    t23 = fma2(Wp[2], A[4], t23);
    t23 = fma2(Wp[3], B[2], t23);
    t23 = fma2(Wp[4], B[3], t23);
    t23 = fma2(Wp[5], B[4], t23);
    t23 = fma2(Wp[6], C[2], t23);
    t23 = fma2(Wp[7], C[3], t23);
    t23 = fma2(Wp[8], C[4], t23);
    t23 = fma2(c015, dd23, t23);

    float t0, t1, t2, t3;
    upk2(t01, t0, t1);
    upk2(t23, t2, t3);
    g[0] = fminf(fmaxf(t0, 1e-4f), 1.0f - 1e-4f);
    g[1] = fminf(fmaxf(t1, 1e-4f), 1.0f - 1e-4f);
    g[2] = fminf(fmaxf(t2, 1e-4f), 1.0f - 1e-4f);
    g[3] = fminf(fmaxf(t3, 1e-4f), 1.0f - 1e-4f);
}

// Packed logistic map: m = g * (3.9 - 3.9 g), written as float4.
__device__ __forceinline__ void map_store(float* __restrict__ dp,
                                          u64 pg01, u64 pg23, u64 c39, u64 cN39)
{
    u64 h01 = fma2(pg01, cN39, c39);
    u64 h23 = fma2(pg23, cN39, c39);
    u64 m01 = mul2(pg01, h01);
    u64 m23 = mul2(pg23, h23);
    float4 mv;
    upk2(m01, mv.x, mv.y);
    upk2(m23, mv.z, mv.w);
    *reinterpret_cast<float4*>(dp) = mv;
}

// Halo block: 4 contiguous rows from R0, predicated by cone + image bounds
// (warp-uniform). Stale rows outside [lo-1,hi+1] never feed computed rows.
__device__ __forceinline__ void halo_block(
    const float* __restrict__ srcb, float* __restrict__ dstb,
    int R0, int lo, int hi, int lane, int x0, int y0,
    const float* __restrict__ dpl, const u64* __restrict__ Wp,
    u64 c015, u64 c39, u64 cN39)
{
    if (R0 > hi || R0 + 3 < lo) return;
    const int yb = y0 - 16 + R0;
    if (yb + 3 < 0 || yb > 255) return;

    const float* pA = srcb + (R0 - 1) * SSTR + 4 + x0;
    u64 A[5], B[5], C[5];
    load6p(pA,        lane, A);
    load6p(pA + SSTR, lane, B);
    #pragma unroll
    for (int i = 0; i < 4; ++i) {
        load6p(pA + (i + 2) * SSTR, lane, C);
        const int r = R0 + i;
        const int y = yb + i;
        if (r >= lo && r <= hi && y >= 0 && y <= 255) {
            const float4 d4 = *reinterpret_cast<const float4*>(dpl + y * 256 + x0);
            const u64 dd01 = pk2(d4.x, d4.y);
            const u64 dd23 = pk2(d4.z, d4.w);
            float g[4];
            taps2(Wp, A, B, C, dd01, dd23, c015, g);
            map_store(dstb + r * SSTR + 4 + x0,
                      pk2(g[0], g[1]), pk2(g[2], g[3]), c39, cN39);
        }
        #pragma unroll
        for (int q = 0; q < 5; ++q) { A[q] = B[q]; B[q] = C[q]; }
    }
}

// Interior block: rows [R0,R0+3] subset of [16,47]; always in-cone ->
// unconditional. Drive pairs live in registers for all 15 steps.
template<bool LAST>
__device__ __forceinline__ void int_block(
    const float* __restrict__ srcb, float* __restrict__ dstb,
    int R0, int lane, int x0, int y0,
    const u64 (&dd01)[4], const u64 (&dd23)[4],
    const u64* __restrict__ Wp, u64 c015, u64 c39, u64 cN39,
    u64 (&sum01)[4], u64 (&sum23)[4], u64 (&sq01)[4], u64 (&sq23)[4],
    float* __restrict__ outBase)
{
    const float* pA = srcb + (R0 - 1) * SSTR + 4 + x0;
    u64 A[5], B[5], C[5];
    load6p(pA,        lane, A);
    load6p(pA + SSTR, lane, B);
    #pragma unroll
    for (int i = 0; i < 4; ++i) {
        load6p(pA + (i + 2) * SSTR, lane, C);
        float g[4];
        taps2(Wp, A, B, C, dd01[i], dd23[i], c015, g);
        const u64 pg01 = pk2(g[0], g[1]);
        const u64 pg23 = pk2(g[2], g[3]);
        sum01[i] = add2(sum01[i], pg01);
        sum23[i] = add2(sum23[i], pg23);
        sq01[i]  = fma2(pg01, pg01, sq01[i]);
        sq23[i]  = fma2(pg23, pg23, sq23[i]);
        if (!LAST) {
            map_store(dstb + (R0 + i) * SSTR + 4 + x0, pg01, pg23, c39, cN39);
        } else {
            const int y = y0 + (R0 - 16) + i;
            const long o = (long)y * 256 + x0;
            *reinterpret_cast<float4*>(outBase + o) =
                make_float4(g[0], g[1], g[2], g[3]);
            float d0, d1, d2, d3;
            upk2(dd01[i], d0, d1);
            upk2(dd23[i], d2, d3);
            const float4 dl = make_float4(g[0] - d0, g[1] - d1,
                                          g[2] - d2, g[3] - d3);
            *reinterpret_cast<float4*>(outBase + 3L * PL + o) = dl;
            *reinterpret_cast<float4*>(outBase + 4L * PL + o) = dl;
        }
        #pragma unroll
        for (int q = 0; q < 5; ++q) { A[q] = B[q]; B[q] = C[q]; }
    }
}

__global__ void __launch_bounds__(512, 1)
cml_fused_kernel(const float* __restrict__ drive,
                 const float* __restrict__ Kl,
                 float* __restrict__ out)
{
    extern __shared__ float smem[];
    float* b0 = smem + SSTR;           // logical row 0 of buffer 0
    float* b1 = smem + NBUF + SSTR;    // logical row 0 of buffer 1

    const int tile = blockIdx.x;       // (b*8 + c)*8 + band
    const int band = tile & 7;
    const int bc   = tile >> 3;
    const int ch   = bc & 7;
    const int y0   = band * 32;
    const float* dpl     = drive + (long)bc * 65536L;
    float*       outBase = out   + (long)bc * 65536L;

    const int tid  = threadIdx.x;
    const int tx   = tid & 63;         // x group (4 columns)
    const int ty   = tid >> 6;         // 0..7, warp-uniform
    const int lane = tid & 31;
    const int x0   = tx << 2;

    // Block ownership: interior quad Ri in [16,47]; halo quad Rh outside.
    const int Ri = (ty < 4) ? (32 + 4 * ty) : (16 + 4 * (ty - 4));
    const int Rh = (ty < 4) ? (4 * ty)      : (48 + 4 * (ty - 4));

    // Folded conv weights, broadcast-packed: W = 0.255*K, +0.595 center.
    u64 Wp[9];
    #pragma unroll
    for (int i = 0; i < 9; ++i) {
        float w = 0.255f * __ldg(&Kl[ch * 9 + i]);
        if (i == 4) w += 0.595f;
        Wp[i] = pk2(w, w);
    }
    const u64 c015 = pk2(0.15f, 0.15f);
    const u64 c39  = pk2(3.9f, 3.9f);
    const u64 cN39 = pk2(-3.9f, -3.9f);

    // Interior drive pairs live in registers for all 15 steps.
    u64 dd01[4], dd23[4];
    #pragma unroll
    for (int i = 0; i < 4; ++i) {
        const int y = y0 + (Ri - 16) + i;
        const float4 d4 = *reinterpret_cast<const float4*>(dpl + y * 256 + x0);
        dd01[i] = pk2(d4.x, d4.y);
        dd23[i] = pk2(d4.z, d4.w);
    }

    // Zero both buffers (guards + out-of-image rows = conv zero padding).
    for (int i = tid; i < 2 * NBUF; i += 512) smem[i] = 0.0f;
    __syncthreads();

    // Init buffer 0 with mapped(drive) on logical rows 1..62 (valid y only).
    for (int idx = tid; idx < 62 * 64; idx += 512) {
        const int r  = 1 + (idx >> 6);
        const int xg = (idx & 63) << 2;
        const int y  = y0 - 16 + r;
        if (y >= 0 && y < 256) {
            const float4 d = *reinterpret_cast<const float4*>(dpl + y * 256 + xg);
            float4 m;
            m.x = (3.9f * d.x) * (1.0f - d.x);
            m.y = (3.9f * d.y) * (1.0f - d.y);
            m.z = (3.9f * d.z) * (1.0f - d.z);
            m.w = (3.9f * d.w) * (1.0f - d.w);
            *reinterpret_cast<float4*>(b0 + r * SSTR + 4 + xg) = m;
        }
    }
    __syncthreads();

    u64 sum01[4], sum23[4], sq01[4], sq23[4];
    const u64 z = pk2(0.0f, 0.0f);
    #pragma unroll
    for (int i = 0; i < 4; ++i) { sum01[i] = z; sum23[i] = z; sq01[i] = z; sq23[i] = z; }

    const float* src = b0;
    float*       dst = b1;
    for (int s = 1; s <= 14; ++s) {
        const int lo = s + 1, hi = 62 - s;
        halo_block(src, dst, Rh, lo, hi, lane, x0, y0, dpl, Wp, c015, c39, cN39);
        int_block<false>(src, dst, Ri, lane, x0, y0, dd01, dd23,
                         Wp, c015, c39, cN39, sum01, sum23, sq01, sq23, outBase);
        const float* t = src; src = dst; dst = const_cast<float*>(t);
        __syncthreads();
    }
    int_block<true>(src, dst, Ri, lane, x0, y0, dd01, dd23,
                    Wp, c015, c39, cN39, sum01, sum23, sq01, sq23, outBase);

    // mean / var from packed accumulators.
    const float inv15 = 1.0f / 15.0f;
    #pragma unroll
    for (int i = 0; i < 4; ++i) {
        const int y = y0 + (Ri - 16) + i;
        const long o = (long)y * 256 + x0;
        float s0, s1, s2, s3, q0, q1, q2, q3;
        upk2(sum01[i], s0, s1); upk2(sum23[i], s2, s3);
        upk2(sq01[i],  q0, q1); upk2(sq23[i],  q2, q3);
        float4 mn, vr;
        mn.x = s0 * inv15; mn.y = s1 * inv15;
        mn.z = s2 * inv15; mn.w = s3 * inv15;
        vr.x = fmaf(-mn.x, mn.x, q0 * inv15);
        vr.y = fmaf(-mn.y, mn.y, q1 * inv15);
        vr.z = fmaf(-mn.z, mn.z, q2 * inv15);
        vr.w = fmaf(-mn.w, mn.w, q3 * inv15);
        *reinterpret_cast<float4*>(outBase + 1L * PL + o) = mn;
        *reinterpret_cast<float4*>(outBase + 2L * PL + o) = vr;
    }
}

extern "C" void kernel_launch(void* const* d_in, const int* in_sizes, int n_in,
                              void* d_out, int out_size)
{
    const float* drive = (const float*)d_in[0];
    const float* Kl    = (const float*)d_in[1];
    if (n_in >= 2 && in_sizes[0] == 72) {         // defensive input-order check
        const float* t = drive; drive = Kl; Kl = t;
    }
    float* out = (float*)d_out;
    (void)out_size;

    const size_t shmem = 2 * NBUF * sizeof(float);   // 139392 bytes
    cudaFuncSetAttribute(cml_fused_kernel,
                         cudaFuncAttributeMaxDynamicSharedMemorySize, (int)shmem);
    cml_fused_kernel<<<1024, 512, shmem>>>(drive, Kl, out);
}